// round 11
// baseline (speedup 1.0000x reference)
#include <cuda_runtime.h>
#include <cstdint>

// Embedding gather: out[token, :] = weight[idx[token], :]
// idx: [8192] int32, weight: [32000, 512] f32, out: [8192, 512] f32
//
// TERMINAL KERNEL — at the hardware floor.
//
// Cold-L2 compulsory-miss gather is capped by L2 miss-tracking recycle:
//   45 MSHR/LTS x 128 B x 184 LTS / ~1040 cyc DRAM latency = ~1.83 TB/s
// Measured 1.85 +/- 0.03 TB/s across 7 distinct mechanisms (scalar LDG,
// smem-staged MLP=8, register MLP=4, TMA bulk copy, L2 cache policies,
// address-sorted banded order, L2 bulk-prefetch pre-pass) and occupancy
// 9%-71%. No cross-launch L2 persistence in this harness (verified 2x),
// so the ~14.7 MB of unique rows are compulsory misses every replay:
//   floor = 14.7 MB / 1.83 TB/s ~= 8.0 us kernel ~= 8.7 us timed.
//
// Shape: 128-thr CTAs, 4 tokens/CTA, grid=2048 (single wave, 16 CTA/SM).
// No smem / no barriers. Front-batched independent gathers (MLP=4),
// fully coalesced LDG.128/STG.128; idx loads are warp-broadcast.

static constexpr int VEC_PER_ROW    = 128;  // 512 f32 = 128 float4
static constexpr int TOKENS_PER_CTA = 4;
static constexpr int THREADS        = 128;

__global__ void __launch_bounds__(THREADS, 16)
embedding_gather_kernel(const int* __restrict__ idx,
                        const float4* __restrict__ weight,
                        float4* __restrict__ out)
{
    const int tid        = threadIdx.x;            // 0..127 = vec within row
    const int base_token = blockIdx.x * TOKENS_PER_CTA;

    // Independent index loads (warp-broadcast, cached).
    int rows[TOKENS_PER_CTA];
#pragma unroll
    for (int k = 0; k < TOKENS_PER_CTA; k++)
        rows[k] = __ldg(&idx[base_token + k]);

    // Front-batched independent gathers: MLP = 4 per thread.
    float4 v[TOKENS_PER_CTA];
#pragma unroll
    for (int k = 0; k < TOKENS_PER_CTA; k++)
        v[k] = __ldg(&weight[(long long)rows[k] * VEC_PER_ROW + tid]);

#pragma unroll
    for (int k = 0; k < TOKENS_PER_CTA; k++)
        out[(long long)(base_token + k) * VEC_PER_ROW + tid] = v[k];
}

extern "C" void kernel_launch(void* const* d_in, const int* in_sizes, int n_in,
                              void* d_out, int out_size)
{
    const int*   idx    = (const int*)d_in[0];    // x: [4, 2048] int32
    const float* weight = (const float*)d_in[1];  // [32000, 512] f32
    float*       out    = (float*)d_out;          // [4, 2048, 512] f32

    const int n_tokens = in_sizes[0];             // 8192
    const int n_ctas   = n_tokens / TOKENS_PER_CTA; // 2048

    embedding_gather_kernel<<<n_ctas, THREADS>>>(
        idx, (const float4*)weight, (float4*)out);
}

// round 12
// speedup vs baseline: 1.0036x; 1.0036x over previous
#include <cuda_runtime.h>
#include <cstdint>

// Hybrid-path embedding gather: even CTAs use LDG.128 demand gathers
// (L1tex miss pool), odd CTAs use cp.async.bulk TMA copies (TMA request
// pool), concurrently in one wave. Discriminates whether the measured
// ~1.85 TB/s cap is per-path (hybrid ~2x faster) or L2/DRAM-shared
// (hybrid neutral).
//
// idx: [8192] int32, weight: [32000, 512] f32 (2 KB/row), out: [8192,512] f32
// grid=2048 x 128 thr, 4 tokens/CTA.

static constexpr int VEC_PER_ROW    = 128;   // 512 f32 = 128 float4
static constexpr int ROW_BYTES      = 2048;
static constexpr int TOKENS_PER_CTA = 4;
static constexpr int THREADS        = 128;
static constexpr int TILE_BYTES     = TOKENS_PER_CTA * ROW_BYTES;  // 8 KB

__global__ void __launch_bounds__(THREADS, 16)
embedding_hybrid_kernel(const int* __restrict__ idx,
                        const float4* __restrict__ weight,
                        float4* __restrict__ out)
{
    __shared__ alignas(128) char buf[TILE_BYTES];
    __shared__ alignas(8) uint64_t mbar;

    const int tid        = threadIdx.x;
    const int base_token = blockIdx.x * TOKENS_PER_CTA;

    if (blockIdx.x & 1) {
        // ---------------- TMA bulk path ----------------
        const int lane = tid & 31;
        if (tid < 32) {
            int row = 0;
            if (lane < TOKENS_PER_CTA)
                row = __ldg(&idx[base_token + lane]);

            const uint32_t smem_buf = (uint32_t)__cvta_generic_to_shared(buf);
            const uint32_t smem_bar = (uint32_t)__cvta_generic_to_shared(&mbar);

            if (lane == 0) {
                asm volatile("mbarrier.init.shared.b64 [%0], 1;"
                             :: "r"(smem_bar) : "memory");
                asm volatile("fence.proxy.async.shared::cta;" ::: "memory");
                asm volatile("mbarrier.arrive.expect_tx.shared.b64 _, [%0], %1;"
                             :: "r"(smem_bar), "r"((uint32_t)TILE_BYTES)
                             : "memory");
            }

#pragma unroll
            for (int k = 0; k < TOKENS_PER_CTA; k++) {
                const int r = __shfl_sync(0xFFFFFFFF, row, k);
                if (lane == 0) {
                    const char* src = (const char*)weight + (long long)r * ROW_BYTES;
                    asm volatile(
                        "cp.async.bulk.shared::cta.global.mbarrier::complete_tx::bytes "
                        "[%0], [%1], %2, [%3];"
                        :: "r"(smem_buf + k * ROW_BYTES), "l"(src),
                           "r"((uint32_t)ROW_BYTES), "r"(smem_bar)
                        : "memory");
                }
            }

            if (lane == 0) {
                uint32_t done = 0;
                while (!done) {
                    asm volatile(
                        "{\n\t"
                        ".reg .pred p;\n\t"
                        "mbarrier.try_wait.parity.shared::cta.b64 p, [%1], %2, 0x989680;\n\t"
                        "selp.b32 %0, 1, 0, p;\n\t"
                        "}"
                        : "=r"(done) : "r"(smem_bar), "r"(0u) : "memory");
                }
                // 4 consecutive tokens -> contiguous 8 KB output tile.
                char* dst = (char*)out + (long long)base_token * ROW_BYTES;
                asm volatile(
                    "cp.async.bulk.global.shared::cta.bulk_group [%0], [%1], %2;"
                    :: "l"(dst), "r"(smem_buf), "r"((uint32_t)TILE_BYTES)
                    : "memory");
                asm volatile("cp.async.bulk.commit_group;" ::: "memory");
                asm volatile("cp.async.bulk.wait_group 0;" ::: "memory");
            }
        }
    } else {
        // ---------------- LDG demand path (champion) ----------------
        int rows[TOKENS_PER_CTA];
#pragma unroll
        for (int k = 0; k < TOKENS_PER_CTA; k++)
            rows[k] = __ldg(&idx[base_token + k]);

        float4 v[TOKENS_PER_CTA];
#pragma unroll
        for (int k = 0; k < TOKENS_PER_CTA; k++)
            v[k] = __ldg(&weight[(long long)rows[k] * VEC_PER_ROW + tid]);

#pragma unroll
        for (int k = 0; k < TOKENS_PER_CTA; k++)
            out[(long long)(base_token + k) * VEC_PER_ROW + tid] = v[k];
    }
}

extern "C" void kernel_launch(void* const* d_in, const int* in_sizes, int n_in,
                              void* d_out, int out_size)
{
    const int*   idx    = (const int*)d_in[0];    // x: [4, 2048] int32
    const float* weight = (const float*)d_in[1];  // [32000, 512] f32
    float*       out    = (float*)d_out;          // [4, 2048, 512] f32

    const int n_tokens = in_sizes[0];             // 8192
    const int n_ctas   = n_tokens / TOKENS_PER_CTA; // 2048

    embedding_hybrid_kernel<<<n_ctas, THREADS>>>(
        idx, (const float4*)weight, (float4*)out);
}

// round 13
// speedup vs baseline: 1.0370x; 1.0333x over previous
#include <cuda_runtime.h>
#include <cstdint>

// Embedding gather: out[token, :] = weight[idx[token], :]
// idx: [8192] int32, weight: [32000, 512] f32, out: [8192, 512] f32
//
// FINAL KERNEL — at the hardware floor.
//
// The read stream (~14.7 MB of unique weight rows, compulsory-miss every
// replay: no cross-launch L2 persistence, verified twice) is pinned at
// the L2 miss-tracking recycle cap:
//   45 MSHR/LTS x 128 B x 184 LTS / ~1040 cyc DRAM latency ~= 1.83 TB/s
// Measured 1.85 +/- 0.05 TB/s across EIGHT mechanisms (scalar LDG,
// smem-staged MLP=8, register MLP=4, TMA bulk copy, L2 cache policies,
// address-sorted banding, L2 prefetch pre-pass, concurrent LDG+TMA
// hybrid) and occupancy 9%-71%. The cap is L2/DRAM-side and shared by
// all request paths. Floor = 14.7 MB / 1.83 TB/s ~= 8.0 us kernel
// ~= 8.7 us timed. Writes are L2-absorbed and do not bind.
//
// Shape: 128-thr CTAs, 4 tokens/CTA, grid=2048 (single wave, 16 CTA/SM).
// No smem / no barriers. Front-batched independent gathers (MLP=4),
// fully coalesced LDG.128/STG.128; idx loads are warp-broadcast.

static constexpr int VEC_PER_ROW    = 128;  // 512 f32 = 128 float4
static constexpr int TOKENS_PER_CTA = 4;
static constexpr int THREADS        = 128;

__global__ void __launch_bounds__(THREADS, 16)
embedding_gather_kernel(const int* __restrict__ idx,
                        const float4* __restrict__ weight,
                        float4* __restrict__ out)
{
    const int tid        = threadIdx.x;            // 0..127 = vec within row
    const int base_token = blockIdx.x * TOKENS_PER_CTA;

    // Independent index loads (warp-broadcast, cached).
    int rows[TOKENS_PER_CTA];
#pragma unroll
    for (int k = 0; k < TOKENS_PER_CTA; k++)
        rows[k] = __ldg(&idx[base_token + k]);

    // Front-batched independent gathers: MLP = 4 per thread.
    float4 v[TOKENS_PER_CTA];
#pragma unroll
    for (int k = 0; k < TOKENS_PER_CTA; k++)
        v[k] = __ldg(&weight[(long long)rows[k] * VEC_PER_ROW + tid]);

#pragma unroll
    for (int k = 0; k < TOKENS_PER_CTA; k++)
        out[(long long)(base_token + k) * VEC_PER_ROW + tid] = v[k];
}

extern "C" void kernel_launch(void* const* d_in, const int* in_sizes, int n_in,
                              void* d_out, int out_size)
{
    const int*   idx    = (const int*)d_in[0];    // x: [4, 2048] int32
    const float* weight = (const float*)d_in[1];  // [32000, 512] f32
    float*       out    = (float*)d_out;          // [4, 2048, 512] f32

    const int n_tokens = in_sizes[0];             // 8192
    const int n_ctas   = n_tokens / TOKENS_PER_CTA; // 2048

    embedding_gather_kernel<<<n_ctas, THREADS>>>(
        idx, (const float4*)weight, (float4*)out);
}